// round 12
// baseline (speedup 1.0000x reference)
#include <cuda_runtime.h>
#include <cuda_fp16.h>

// LocalPosEnc2D: bilinear grid sample (513x513 x 24ch, fp32) + sinusoidal PE gating.
//   coords: (B,2) fp32   grids: (513*513, 24) fp32   out: (B,24) fp32
// 12-lanes-per-point layout: one LDG.128 covers a whole 192B corner-pair
// segment (rows idx, idx+1), halving gather instructions and cutting L1
// wavefronts/point ~7 -> ~5. Each lane v-interps its chunk; one float4
// shuffle brings the right-column result to lanes m<6 for the u-interp,
// PE gating, and store. Warp = 24 active lanes = 2 points x 3 iterations.

#define GRID_ELEMS (513 * 513 * 24)
#define TWO_PI_F 6.28318530717958647692f
#define PI_F     3.14159265358979323846f
#define ACTIVE_MASK 0x00FFFFFFu

__device__ __forceinline__ void setup_point(
    const float2& c, float& lu, float& lv, int& idx00)
{
    float u = fminf(fmaxf(c.x, 0.0f), 1.0f - 1e-6f);
    float v = fminf(fmaxf(c.y, 0.0f), 1.0f - 1e-6f);
    float fu = u * 512.0f;
    float fv = v * 512.0f;
    int iu = (int)fu; iu = iu > 511 ? 511 : iu;
    int iv = (int)fv; iv = iv > 511 ? 511 : iv;
    lu = fu - (float)iu;
    lv = fv - (float)iv;
    idx00 = iu + iv * 513;
}

// One point-iteration: all 24 lanes v-interp, shuffle, lanes m<6 finish.
__device__ __forceinline__ void lpe_iter(
    float lu, float lv, int lane, int m, int j,
    const float4& fA, const float4& fB,
    bool do_store, float4* outp)
{
    float wv0 = 1.0f - lv;
    float4 g;
    g.x = fA.x * wv0 + fB.x * lv;
    g.y = fA.y * wv0 + fB.y * lv;
    g.z = fA.z * wv0 + fB.z * lv;
    g.w = fA.w * wv0 + fB.w * lv;

    // Bring right-column (u=iu+1) interp from lane m+6 to lanes m<6.
    int src = (m < 6) ? (lane + 6) : lane;
    float4 h;
    h.x = __shfl_sync(ACTIVE_MASK, g.x, src);
    h.y = __shfl_sync(ACTIVE_MASK, g.y, src);
    h.z = __shfl_sync(ACTIVE_MASK, g.z, src);
    h.w = __shfl_sync(ACTIVE_MASK, g.w, src);

    if (m < 6 && do_store) {
        // PE gates. j=0,1 base (gate 1); j=2: cos(2^k*2pi*lu) j=3: sin(..lu)
        // j=4: cos(..lv) j=5: sin(..lv)
        float l = (j < 4) ? lu : lv;
        float ang = fmaf(l, TWO_PI_F, -PI_F);        // [-pi, pi)
        float s0 = -__sinf(ang);
        float c0 = -__cosf(ang);
        float s1 = 2.0f * s0 * c0;
        float c1 = fmaf(2.0f * c0, c0, -1.0f);
        float s2 = 2.0f * s1 * c1;
        float c2 = fmaf(2.0f * c1, c1, -1.0f);
        float s3 = 2.0f * s2 * c2;
        float c3 = fmaf(2.0f * c2, c2, -1.0f);

        bool use_sin = (j & 1);
        float pe0 = use_sin ? s0 : c0;
        float pe1 = use_sin ? s1 : c1;
        float pe2 = use_sin ? s2 : c2;
        float pe3 = use_sin ? s3 : c3;
        if (j < 2) { pe0 = 1.0f; pe1 = 1.0f; pe2 = 1.0f; pe3 = 1.0f; }

        float wu0 = 1.0f - lu;
        float4 o;
        o.x = __half2float(__float2half_rn((g.x * wu0 + h.x * lu) * pe0));
        o.y = __half2float(__float2half_rn((g.y * wu0 + h.y * lu) * pe1));
        o.z = __half2float(__float2half_rn((g.z * wu0 + h.z * lu) * pe2));
        o.w = __half2float(__float2half_rn((g.w * wu0 + h.w * lu) * pe3));
        __stcs(outp, o);
    }
}

__global__ __launch_bounds__(256) void lpe2d_kernel(
    const float2* __restrict__ coords,
    const float4* __restrict__ grids,   // grid row = 6 float4 (24 floats)
    float4*       __restrict__ out,     // out row  = 6 float4 (24 floats)
    int B)
{
    int gwarp = (blockIdx.x * blockDim.x + threadIdx.x) >> 5;
    int lane  = threadIdx.x & 31;
    if (lane >= 24) return;             // 24 active lanes: 2 points/iteration
    int q = lane / 12;                  // point slot 0..1
    int m = lane - q * 12;              // chunk 0..11 within 192B segment
    int j = (m >= 6) ? (m - 6) : m;     // channel chunk role 0..5

    int pb = gwarp * 6 + q;             // points pb, pb+2, pb+4
    int p0 = pb;
    int p1 = pb + 2;
    int p2 = pb + 4;
    int Bm1 = B - 1;
    int p0c = p0 > Bm1 ? Bm1 : p0;
    int p1c = p1 > Bm1 ? Bm1 : p1;
    int p2c = p2 > Bm1 ? Bm1 : p2;

    // Coord loads (12-lane broadcast each).
    float2 c0 = coords[p0c];
    float2 c1 = coords[p1c];
    float2 c2 = coords[p2c];

    float lu0, lv0, lu1, lv1, lu2, lv2;
    int i0, i1, i2;
    setup_point(c0, lu0, lv0, i0);
    setup_point(c1, lu1, lv1, i1);
    setup_point(c2, lu2, lv2, i2);

    // Segment A = rows (iv, iv+1) of column iu..iu+1 block: 192B contiguous.
    // Segment B = rows (iv+1's v-neighbor): grids + (idx+513)*6, 192B.
    const float4* sA0 = grids + (size_t)i0 * 6;
    const float4* sB0 = grids + (size_t)(i0 + 513) * 6;
    const float4* sA1 = grids + (size_t)i1 * 6;
    const float4* sB1 = grids + (size_t)(i1 + 513) * 6;
    const float4* sA2 = grids + (size_t)i2 * 6;
    const float4* sB2 = grids + (size_t)(i2 + 513) * 6;

    // Issue all 6 gathers up front (each LDG.128 covers one full 192B
    // segment across 12 lanes; 2 segments per warp instruction).
    float4 fA0 = sA0[m];
    float4 fB0 = sB0[m];
    float4 fA1 = sA1[m];
    float4 fB1 = sB1[m];
    float4 fA2 = sA2[m];
    float4 fB2 = sB2[m];

    lpe_iter(lu0, lv0, lane, m, j, fA0, fB0, p0 < B, out + (size_t)p0c * 6 + j);
    lpe_iter(lu1, lv1, lane, m, j, fA1, fB1, p1 < B, out + (size_t)p1c * 6 + j);
    lpe_iter(lu2, lv2, lane, m, j, fA2, fB2, p2 < B, out + (size_t)p2c * 6 + j);
}

extern "C" void kernel_launch(void* const* d_in, const int* in_sizes, int n_in,
                              void* d_out, int out_size) {
    // Bind inputs by size: grids has exactly 513*513*24 elements.
    int gi = -1, ci = -1;
    for (int i = 0; i < n_in; i++)
        if (in_sizes[i] == GRID_ELEMS && gi < 0) gi = i;
    for (int i = 0; i < n_in; i++)
        if (i != gi && ci < 0) ci = i;
    if (gi < 0) { gi = 1; ci = 0; }

    const float2* coords = (const float2*)d_in[ci];
    const float4* grids  = (const float4*)d_in[gi];
    float4*       out    = (float4*)d_out;
    int B = out_size / 24;                          // out is (B, 24) fp32
    long long warps = ((long long)B + 5) / 6;       // 6 points per warp
    long long threads_total = warps * 32;
    int threads = 256;
    int blocks = (int)((threads_total + threads - 1) / threads);
    lpe2d_kernel<<<blocks, threads>>>(coords, grids, out, B);
}

// round 13
// speedup vs baseline: 1.6343x; 1.6343x over previous
#include <cuda_runtime.h>
#include <cuda_fp16.h>

// LocalPosEnc2D: bilinear grid sample (513x513 x 24ch, fp32) + sinusoidal PE gating.
//   coords: (B,2) fp32   grids: (513*513, 24) fp32   out: (B,24) fp32
// Warp-aligned cooperative layout, 2 points per thread:
// warp owns 10 points; lane l<30 -> role j=l%6 (channels 4j..4j+3), local
// q=l/6; handles points warp*10+q and warp*10+q+5. All 8 gathers issued
// before any consumption; trig for both points computed in the shadow of
// the loads. __launch_bounds__(256,2) raises the register ceiling so ptxas
// can keep all 8 loads in flight (R10/R11 collapsed to 32 regs = serialized).

#define GRID_ELEMS (513 * 513 * 24)
#define TWO_PI_F 6.28318530717958647692f
#define PI_F     3.14159265358979323846f

__device__ __forceinline__ void setup_point(
    const float2& c, float& lu, float& lv, int& idx00)
{
    float u = fminf(fmaxf(c.x, 0.0f), 1.0f - 1e-6f);
    float v = fminf(fmaxf(c.y, 0.0f), 1.0f - 1e-6f);
    float fu = u * 512.0f;
    float fv = v * 512.0f;
    int iu = (int)fu; iu = iu > 511 ? 511 : iu;
    int iv = (int)fv; iv = iv > 511 ? 511 : iv;
    lu = fu - (float)iu;
    lv = fv - (float)iv;
    idx00 = iu + iv * 513;
}

// PE gates for lane role j at local coords (lu,lv).
__device__ __forceinline__ void pe_gates(
    float lu, float lv, int j,
    float& pe0, float& pe1, float& pe2, float& pe3)
{
    // j=0,1 base (gate 1); j=2: cos(2^k*2pi*lu) j=3: sin(..lu)
    // j=4: cos(..lv) j=5: sin(..lv)
    float l = (j < 4) ? lu : lv;
    float ang = fmaf(l, TWO_PI_F, -PI_F);        // [-pi, pi)
    float s0 = -__sinf(ang);                     // sin(2*pi*l)
    float c0 = -__cosf(ang);                     // cos(2*pi*l)
    float s1 = 2.0f * s0 * c0;
    float c1 = fmaf(2.0f * c0, c0, -1.0f);
    float s2 = 2.0f * s1 * c1;
    float c2 = fmaf(2.0f * c1, c1, -1.0f);
    float s3 = 2.0f * s2 * c2;
    float c3 = fmaf(2.0f * c2, c2, -1.0f);

    bool use_sin = (j & 1);
    pe0 = use_sin ? s0 : c0;
    pe1 = use_sin ? s1 : c1;
    pe2 = use_sin ? s2 : c2;
    pe3 = use_sin ? s3 : c3;
    if (j < 2) { pe0 = 1.0f; pe1 = 1.0f; pe2 = 1.0f; pe3 = 1.0f; }
}

__device__ __forceinline__ void bilerp_store(
    float lu, float lv,
    const float4& a, const float4& bq, const float4& cq, const float4& dq,
    float pe0, float pe1, float pe2, float pe3,
    float4* outp)
{
    float wu0 = 1.0f - lu, wv0 = 1.0f - lv;
    float4 o;
    float t, b;
    t = a.x * wu0 + bq.x * lu;  b = cq.x * wu0 + dq.x * lu;
    o.x = __half2float(__float2half_rn((t * wv0 + b * lv) * pe0));
    t = a.y * wu0 + bq.y * lu;  b = cq.y * wu0 + dq.y * lu;
    o.y = __half2float(__float2half_rn((t * wv0 + b * lv) * pe1));
    t = a.z * wu0 + bq.z * lu;  b = cq.z * wu0 + dq.z * lu;
    o.z = __half2float(__float2half_rn((t * wv0 + b * lv) * pe2));
    t = a.w * wu0 + bq.w * lu;  b = cq.w * wu0 + dq.w * lu;
    o.w = __half2float(__float2half_rn((t * wv0 + b * lv) * pe3));
    __stcs(outp, o);
}

__global__ __launch_bounds__(256, 2) void lpe2d_kernel(
    const float2* __restrict__ coords,
    const float4* __restrict__ grids,   // grid row = 6 float4 (24 floats)
    float4*       __restrict__ out,     // out row  = 6 float4 (24 floats)
    int B)
{
    int gwarp = (blockIdx.x * blockDim.x + threadIdx.x) >> 5;
    int lane  = threadIdx.x & 31;
    if (lane >= 30) return;             // 2 idle lanes per warp (no straddle)
    int q = lane / 6;                   // local point 0..4
    int j = lane - q * 6;               // chunk role 0..5

    int p0 = gwarp * 10 + q;
    int p1 = p0 + 5;
    if (p0 >= B) return;
    bool has1 = (p1 < B);

    // Coord loads (broadcast within each 6-lane group).
    float2 c0 = coords[p0];
    float2 c1 = coords[has1 ? p1 : p0];

    float lu0, lv0, lu1, lv1;
    int i0, i1;
    setup_point(c0, lu0, lv0, i0);
    setup_point(c1, lu1, lv1, i1);

    const float4* r00 = grids + (size_t)i0 * 6;          // p0 rows iv   (192B)
    const float4* r01 = grids + (size_t)(i0 + 513) * 6;  // p0 rows iv+1
    const float4* r10 = grids + (size_t)i1 * 6;
    const float4* r11 = grids + (size_t)(i1 + 513) * 6;

    // Issue all 8 gathers before any use (MLP=8).
    float4 a0 = r00[j];
    float4 b0 = r00[j + 6];
    float4 g0 = r01[j];
    float4 d0 = r01[j + 6];
    float4 a1 = r10[j];
    float4 b1 = r10[j + 6];
    float4 g1 = r11[j];
    float4 d1 = r11[j + 6];

    // Trig for BOTH points in the shadow of the in-flight loads.
    float pe00, pe01, pe02, pe03, pe10, pe11, pe12, pe13;
    pe_gates(lu0, lv0, j, pe00, pe01, pe02, pe03);
    pe_gates(lu1, lv1, j, pe10, pe11, pe12, pe13);

    bilerp_store(lu0, lv0, a0, b0, g0, d0, pe00, pe01, pe02, pe03,
                 out + (size_t)p0 * 6 + j);
    if (has1)
        bilerp_store(lu1, lv1, a1, b1, g1, d1, pe10, pe11, pe12, pe13,
                     out + (size_t)p1 * 6 + j);
}

extern "C" void kernel_launch(void* const* d_in, const int* in_sizes, int n_in,
                              void* d_out, int out_size) {
    // Bind inputs by size: grids has exactly 513*513*24 elements.
    int gi = -1, ci = -1;
    for (int i = 0; i < n_in; i++)
        if (in_sizes[i] == GRID_ELEMS && gi < 0) gi = i;
    for (int i = 0; i < n_in; i++)
        if (i != gi && ci < 0) ci = i;
    if (gi < 0) { gi = 1; ci = 0; }

    const float2* coords = (const float2*)d_in[ci];
    const float4* grids  = (const float4*)d_in[gi];
    float4*       out    = (float4*)d_out;
    int B = out_size / 24;                          // out is (B, 24) fp32
    long long warps = ((long long)B + 9) / 10;      // 10 points per warp
    long long threads_total = warps * 32;
    int threads = 256;
    int blocks = (int)((threads_total + threads - 1) / threads);
    lpe2d_kernel<<<blocks, threads>>>(coords, grids, out, B);
}